// round 9
// baseline (speedup 1.0000x reference)
#include <cuda_runtime.h>

#define NN 100000
#define NE 1600000
#define D  64
#define H  4
#define C  16
#define HC 64
#define ALPHA 0.2f
#define SHIFT 10.0f   // fixed softmax shift (replaces per-segment max; shift-invariant)

// Scratch (no cudaMalloc allowed) — device globals.
__device__ float g_q[NN * HC];        // 25.6 MB
__device__ float g_v[NN * HC];        // 25.6 MB
__device__ float g_denom[NN * H];     // 1.6 MB
__device__ float g_akT[H * C];        // transposed attention kernel [h][c]

__device__ __forceinline__ float lrelu(float x) { return x > 0.f ? x : ALPHA * x; }

// Vectorized global reduction (sm_90+): one instruction, 16B, no return value.
__device__ __forceinline__ void red_add_v4(float* addr, float a, float b, float c, float d) {
    asm volatile("red.global.add.v4.f32 [%0], {%1,%2,%3,%4};"
                 :: "l"(addr), "f"(a), "f"(b), "f"(c), "f"(d) : "memory");
}

// ---------------- init: zero out + denom, transpose ak (grid-stride) ----------------
__global__ void k_init(float* __restrict__ out, const float* __restrict__ ak) {
    for (int i = blockIdx.x * blockDim.x + threadIdx.x; i < NN * HC;
         i += gridDim.x * blockDim.x) {
        out[i] = 0.f;
        if (i < NN * H) g_denom[i] = 0.f;
        if (i < H * C) {                   // i = h*C + c  <-  ak[c*H + h]
            int h = i / C, c = i % C;
            g_akT[i] = ak[c * H + h];
        }
    }
}

// ---------------- node GEMMs: q = xWq+bq, v = xWv+bv ----------------
// One warp handles 4 nodes. Lanes 0..15 produce q columns (float4 groups),
// lanes 16..31 produce v columns. W float4 loads amortized over 4 nodes.
#define NPW 4
#define GEMM_WARPS 8
__global__ __launch_bounds__(256) void k_gemm(
    const float* __restrict__ x,
    const float* __restrict__ Wq, const float* __restrict__ bq,
    const float* __restrict__ Wv, const float* __restrict__ bv)
{
    __shared__ float sx[GEMM_WARPS * NPW][D];  // 32 x 64 floats = 8 KB
    const int tid  = threadIdx.x;
    const int warp = tid >> 5, lane = tid & 31;
    const int node0 = blockIdx.x * (GEMM_WARPS * NPW);

    // cooperative load of 32 node rows (2048 floats = 512 float4)
    {
        const float4* xin = (const float4*)(x + (size_t)node0 * D);
        float4* s4 = (float4*)&sx[0][0];
        for (int i = tid; i < GEMM_WARPS * NPW * (D / 4); i += 256)
            s4[i] = xin[i];
    }
    __syncthreads();

    const bool isQ = lane < 16;
    const int  colg = isQ ? lane : lane - 16;          // which float4 of 64 cols
    const float4* W4 = (const float4*)(isQ ? Wq : Wv); // row-major [64 x 64]
    const float4  b4 = ((const float4*)(isQ ? bq : bv))[colg];

    float4 acc[NPW];
#pragma unroll
    for (int n = 0; n < NPW; n++) acc[n] = make_float4(0.f, 0.f, 0.f, 0.f);

    const int nbase = warp * NPW;
#pragma unroll 8
    for (int k = 0; k < D; k++) {
        float4 w = W4[k * (D / 4) + colg];
#pragma unroll
        for (int n = 0; n < NPW; n++) {
            float xk = sx[nbase + n][k];   // warp-uniform -> smem broadcast
            acc[n].x += xk * w.x; acc[n].y += xk * w.y;
            acc[n].z += xk * w.z; acc[n].w += xk * w.w;
        }
    }

#pragma unroll
    for (int n = 0; n < NPW; n++) {
        int node = node0 + nbase + n;
        if (node >= NN) break;
        float4 r = make_float4(acc[n].x + b4.x, acc[n].y + b4.y,
                               acc[n].z + b4.z, acc[n].w + b4.w);
        float4* outp = (float4*)((isQ ? g_q : g_v) + (size_t)node * HC) + colg;
        *outp = r;
    }
}

// ------- fused per-edge pass: logits -> exp -> REDG denom + REDG ex*v -------
// v[s] rows are already in registers for the logit; reuse them for the
// unnormalized scatter. Normalization deferred to k_final (division
// distributes over the segment sum exactly).
__global__ __launch_bounds__(128) void k_edge(
    const int* __restrict__ esrc, const int* __restrict__ etgt,
    float* __restrict__ out)
{
    int e = blockIdx.x * blockDim.x + threadIdx.x;
    if (e >= NE) return;
    const int t = __ldg(&etgt[e]), s = __ldg(&esrc[e]);
    const float4* qp = (const float4*)(g_q + (size_t)t * HC);
    const float4* vp = (const float4*)(g_v + (size_t)s * HC);
    float* op = out + (size_t)t * HC;

    float exh[H];
#pragma unroll
    for (int h = 0; h < H; h++) {
        const float4* ap = (const float4*)(g_akT + h * C);
        // batched loads for this head (MLP=8)
        float4 q0 = __ldg(qp + h * 4 + 0), q1 = __ldg(qp + h * 4 + 1),
               q2 = __ldg(qp + h * 4 + 2), q3 = __ldg(qp + h * 4 + 3);
        float4 v0 = __ldg(vp + h * 4 + 0), v1 = __ldg(vp + h * 4 + 1),
               v2 = __ldg(vp + h * 4 + 2), v3 = __ldg(vp + h * 4 + 3);
        float4 a0 = __ldg(ap + 0), a1 = __ldg(ap + 1),
               a2 = __ldg(ap + 2), a3 = __ldg(ap + 3);

        float acc = 0.f;
        acc += lrelu(q0.x + v0.x) * a0.x; acc += lrelu(q0.y + v0.y) * a0.y;
        acc += lrelu(q0.z + v0.z) * a0.z; acc += lrelu(q0.w + v0.w) * a0.w;
        acc += lrelu(q1.x + v1.x) * a1.x; acc += lrelu(q1.y + v1.y) * a1.y;
        acc += lrelu(q1.z + v1.z) * a1.z; acc += lrelu(q1.w + v1.w) * a1.w;
        acc += lrelu(q2.x + v2.x) * a2.x; acc += lrelu(q2.y + v2.y) * a2.y;
        acc += lrelu(q2.z + v2.z) * a2.z; acc += lrelu(q2.w + v2.w) * a2.w;
        acc += lrelu(q3.x + v3.x) * a3.x; acc += lrelu(q3.y + v3.y) * a3.y;
        acc += lrelu(q3.z + v3.z) * a3.z; acc += lrelu(q3.w + v3.w) * a3.w;

        const float ex = __expf(acc - SHIFT);
        exh[h] = ex;

        // unnormalized weighted scatter: out[t] += ex * v[s]  (v reused from regs)
        float* o = op + h * C;
        red_add_v4(o +  0, ex * v0.x, ex * v0.y, ex * v0.z, ex * v0.w);
        red_add_v4(o +  4, ex * v1.x, ex * v1.y, ex * v1.z, ex * v1.w);
        red_add_v4(o +  8, ex * v2.x, ex * v2.y, ex * v2.z, ex * v2.w);
        red_add_v4(o + 12, ex * v3.x, ex * v3.y, ex * v3.z, ex * v3.w);
    }

    red_add_v4(&g_denom[t * H], exh[0], exh[1], exh[2], exh[3]);
}

// ------- final: normalize by segment denom, then leaky_relu (grid-stride) -------
__global__ void k_final(float* __restrict__ out) {
    float4* o4 = (float4*)out;
    const int n4 = NN * HC / 4;                 // one float4 = 4 channels of a head
    for (int i = blockIdx.x * blockDim.x + threadIdx.x; i < n4;
         i += gridDim.x * blockDim.x) {
        // element index i*4 .. i*4+3 share head: denom idx = (i*4)/C = i/4
        float d = g_denom[i >> 2];
        float r = (d > 0.f) ? __frcp_rn(d) : 1.f;
        float4 v = o4[i];
        v.x *= r; v.y *= r; v.z *= r; v.w *= r;
        v.x = lrelu(v.x); v.y = lrelu(v.y); v.z = lrelu(v.z); v.w = lrelu(v.w);
        o4[i] = v;
    }
}

extern "C" void kernel_launch(void* const* d_in, const int* in_sizes, int n_in,
                              void* d_out, int out_size) {
    const float* x    = (const float*)d_in[0];
    const float* Wq   = (const float*)d_in[1];
    const float* bq   = (const float*)d_in[2];
    const float* Wv   = (const float*)d_in[3];
    const float* bv   = (const float*)d_in[4];
    const float* ak   = (const float*)d_in[5];
    const int*   esrc = (const int*)d_in[6];
    const int*   etgt = (const int*)d_in[7];
    float* out = (float*)d_out;

    k_init<<<1024, 256>>>(out, ak);
    k_gemm<<<(NN + GEMM_WARPS * NPW - 1) / (GEMM_WARPS * NPW), 256>>>(x, Wq, bq, Wv, bv);
    k_edge<<<(NE + 127) / 128, 128>>>(esrc, etgt, out);
    k_final<<<1024, 256>>>(out);
}

// round 17
// speedup vs baseline: 2.3040x; 2.3040x over previous
#include <cuda_runtime.h>

#define NN 100000
#define NE 1600000
#define D  64
#define H  4
#define C  16
#define HC 64
#define ALPHA 0.2f
#define SHIFT 10.0f   // fixed softmax shift (shift-invariant vs per-segment max)

#define SCAN_B 1024
#define NB ((NN + SCAN_B - 1) / SCAN_B)   // 98 scan blocks

// Scratch (no cudaMalloc allowed) — device globals.
__device__ float g_q[NN * HC];        // 25.6 MB
__device__ float g_v[NN * HC];        // 25.6 MB
__device__ float g_akT[H * C];        // transposed attention kernel [h*16+c]
__device__ int   g_cnt[NN];           // degree (by target)
__device__ int   g_rowt[NN];          // per-block exclusive scan
__device__ int   g_row[NN];           // CSR row start
__device__ int   g_cur[NN];           // fill cursor
__device__ int   g_bsum[NB + 32];     // scan block sums
__device__ int   g_boff[NB + 32];     // scanned block offsets
__device__ int   g_srcCSR[NE];        // source node per CSR slot

__device__ __forceinline__ float lrelu(float x) { return x > 0.f ? x : ALPHA * x; }

// ---------------- init: zero degree counters, transpose ak ----------------
__global__ void k_init(const float* __restrict__ ak) {
    for (int i = blockIdx.x * blockDim.x + threadIdx.x; i < NN;
         i += gridDim.x * blockDim.x) {
        g_cnt[i] = 0;
        if (i < H * C) {                   // i = h*C + c  <-  ak[c*H + h]
            int h = i / C, c = i % C;
            g_akT[i] = ak[c * H + h];
        }
    }
}

// ---------------- node GEMMs: q = xWq+bq, v = xWv+bv ----------------
#define NPW 4
#define GEMM_WARPS 8
__global__ __launch_bounds__(256) void k_gemm(
    const float* __restrict__ x,
    const float* __restrict__ Wq, const float* __restrict__ bq,
    const float* __restrict__ Wv, const float* __restrict__ bv)
{
    __shared__ float sx[GEMM_WARPS * NPW][D];  // 8 KB
    const int tid  = threadIdx.x;
    const int warp = tid >> 5, lane = tid & 31;
    const int node0 = blockIdx.x * (GEMM_WARPS * NPW);

    {
        const float4* xin = (const float4*)(x + (size_t)node0 * D);
        float4* s4 = (float4*)&sx[0][0];
        for (int i = tid; i < GEMM_WARPS * NPW * (D / 4); i += 256)
            s4[i] = xin[i];
    }
    __syncthreads();

    const bool isQ = lane < 16;
    const int  colg = isQ ? lane : lane - 16;
    const float4* W4 = (const float4*)(isQ ? Wq : Wv);
    const float4  b4 = ((const float4*)(isQ ? bq : bv))[colg];

    float4 acc[NPW];
#pragma unroll
    for (int n = 0; n < NPW; n++) acc[n] = make_float4(0.f, 0.f, 0.f, 0.f);

    const int nbase = warp * NPW;
#pragma unroll 8
    for (int k = 0; k < D; k++) {
        float4 w = W4[k * (D / 4) + colg];
#pragma unroll
        for (int n = 0; n < NPW; n++) {
            float xk = sx[nbase + n][k];
            acc[n].x += xk * w.x; acc[n].y += xk * w.y;
            acc[n].z += xk * w.z; acc[n].w += xk * w.w;
        }
    }

#pragma unroll
    for (int n = 0; n < NPW; n++) {
        int node = node0 + nbase + n;
        if (node >= NN) break;
        float4 r = make_float4(acc[n].x + b4.x, acc[n].y + b4.y,
                               acc[n].z + b4.z, acc[n].w + b4.w);
        float4* outp = (float4*)((isQ ? g_q : g_v) + (size_t)node * HC) + colg;
        *outp = r;
    }
}

// ---------------- CSR build: histogram ----------------
__global__ void k_hist(const int* __restrict__ etgt) {
    for (int e = blockIdx.x * blockDim.x + threadIdx.x; e < NE;
         e += gridDim.x * blockDim.x)
        atomicAdd(&g_cnt[__ldg(&etgt[e])], 1);
}

// ---------------- CSR build: 2-level exclusive scan ----------------
__global__ __launch_bounds__(SCAN_B) void k_scan1() {
    __shared__ int sh[SCAN_B];
    const int t = threadIdx.x;
    const int i = blockIdx.x * SCAN_B + t;
    int val = (i < NN) ? g_cnt[i] : 0;
    sh[t] = val;
    __syncthreads();
    for (int off = 1; off < SCAN_B; off <<= 1) {
        int x = (t >= off) ? sh[t - off] : 0;
        __syncthreads();
        sh[t] += x;
        __syncthreads();
    }
    if (i < NN) g_rowt[i] = sh[t] - val;             // exclusive
    if (t == SCAN_B - 1) g_bsum[blockIdx.x] = sh[t]; // block total
}

__global__ __launch_bounds__(128) void k_scan2() {
    __shared__ int sh[128];
    const int t = threadIdx.x;
    int val = (t < NB) ? g_bsum[t] : 0;
    sh[t] = val;
    __syncthreads();
    for (int off = 1; off < 128; off <<= 1) {
        int x = (t >= off) ? sh[t - off] : 0;
        __syncthreads();
        sh[t] += x;
        __syncthreads();
    }
    if (t < NB) g_boff[t] = sh[t] - val;             // exclusive
}

__global__ void k_scan3() {
    for (int i = blockIdx.x * blockDim.x + threadIdx.x; i < NN;
         i += gridDim.x * blockDim.x) {
        int r = g_rowt[i] + g_boff[i / SCAN_B];
        g_row[i] = r;
        g_cur[i] = r;
    }
}

// ---------------- CSR build: scatter source ids into rows ----------------
__global__ void k_fill(const int* __restrict__ esrc, const int* __restrict__ etgt) {
    for (int e = blockIdx.x * blockDim.x + threadIdx.x; e < NE;
         e += gridDim.x * blockDim.x) {
        int t = __ldg(&etgt[e]);
        int slot = atomicAdd(&g_cur[t], 1);
        g_srcCSR[slot] = __ldg(&esrc[e]);
    }
}

// ------- gather-side aggregation: one warp per target node, no out atomics -------
// lane owns channels {2*lane, 2*lane+1}; head h = lane/8 (lanes 8h..8h+7).
// Two edges per iteration: independent shfl->exp chains overlap.
__global__ __launch_bounds__(256) void k_aggr(float* __restrict__ out) {
    const int n = (blockIdx.x * blockDim.x + threadIdx.x) >> 5;   // node id
    if (n >= NN) return;                                           // whole warp exits
    const int lane = threadIdx.x & 31;

    const float2 ql = __ldg((const float2*)(g_q + (size_t)n * HC + 2 * lane));
    const float2 al = __ldg((const float2*)(g_akT + 2 * lane));

    const int beg = __ldg(&g_row[n]);
    const int deg = __ldg(&g_cnt[n]);

    float accx = 0.f, accy = 0.f, exsum = 0.f;

    int k = 0;
    for (; k + 2 <= deg; k += 2) {
        // two independent edges: loads and reduce chains interleave
        const int sA = __ldg(&g_srcCSR[beg + k]);
        const int sB = __ldg(&g_srcCSR[beg + k + 1]);
        const float2 vA = __ldg((const float2*)(g_v + (size_t)sA * HC + 2 * lane));
        const float2 vB = __ldg((const float2*)(g_v + (size_t)sB * HC + 2 * lane));

        float pA = lrelu(ql.x + vA.x) * al.x + lrelu(ql.y + vA.y) * al.y;
        float pB = lrelu(ql.x + vB.x) * al.x + lrelu(ql.y + vB.y) * al.y;
        pA += __shfl_xor_sync(0xffffffffu, pA, 1);
        pB += __shfl_xor_sync(0xffffffffu, pB, 1);
        pA += __shfl_xor_sync(0xffffffffu, pA, 2);
        pB += __shfl_xor_sync(0xffffffffu, pB, 2);
        pA += __shfl_xor_sync(0xffffffffu, pA, 4);
        pB += __shfl_xor_sync(0xffffffffu, pB, 4);
        const float exA = __expf(pA - SHIFT);
        const float exB = __expf(pB - SHIFT);

        exsum += exA + exB;
        accx += exA * vA.x + exB * vB.x;
        accy += exA * vA.y + exB * vB.y;
    }
    if (k < deg) {   // odd-degree tail
        const int sA = __ldg(&g_srcCSR[beg + k]);
        const float2 vA = __ldg((const float2*)(g_v + (size_t)sA * HC + 2 * lane));
        float pA = lrelu(ql.x + vA.x) * al.x + lrelu(ql.y + vA.y) * al.y;
        pA += __shfl_xor_sync(0xffffffffu, pA, 1);
        pA += __shfl_xor_sync(0xffffffffu, pA, 2);
        pA += __shfl_xor_sync(0xffffffffu, pA, 4);
        const float exA = __expf(pA - SHIFT);
        exsum += exA;
        accx += exA * vA.x;
        accy += exA * vA.y;
    }

    const float r = (exsum > 0.f) ? __frcp_rn(exsum) : 1.f;
    float2 o;
    o.x = lrelu(accx * r);
    o.y = lrelu(accy * r);
    *(float2*)(out + (size_t)n * HC + 2 * lane) = o;
}

extern "C" void kernel_launch(void* const* d_in, const int* in_sizes, int n_in,
                              void* d_out, int out_size) {
    const float* x    = (const float*)d_in[0];
    const float* Wq   = (const float*)d_in[1];
    const float* bq   = (const float*)d_in[2];
    const float* Wv   = (const float*)d_in[3];
    const float* bv   = (const float*)d_in[4];
    const float* ak   = (const float*)d_in[5];
    const int*   esrc = (const int*)d_in[6];
    const int*   etgt = (const int*)d_in[7];
    float* out = (float*)d_out;

    k_init<<<256, 256>>>(ak);
    k_gemm<<<(NN + GEMM_WARPS * NPW - 1) / (GEMM_WARPS * NPW), 256>>>(x, Wq, bq, Wv, bv);
    k_hist<<<1024, 256>>>(etgt);
    k_scan1<<<NB, SCAN_B>>>();
    k_scan2<<<1, 128>>>();
    k_scan3<<<256, 256>>>();
    k_fill<<<1024, 256>>>(esrc, etgt);
    k_aggr<<<(NN * 32 + 255) / 256, 256>>>(out);
}